// round 1
// baseline (speedup 1.0000x reference)
#include <cuda_runtime.h>
#include <cstdint>

// Problem constants (fixed by the reference)
#define BB 8
#define CC 128
#define HH 128
#define WW 128
#define PP 32768
#define HW (HH * WW)

// Scratch: feat_grid transposed to [B, H*W, C] (channels-last). 67 MB.
__device__ float g_featT[BB * HW * CC];

// ---------------------------------------------------------------------------
// Kernel 1: tiled transpose per batch:  src[C][HW] -> dst[HW][C]
// grid: (HW/32, C/32, B), block: (32, 8)
// ---------------------------------------------------------------------------
__global__ void transpose_kernel(const float* __restrict__ src) {
    __shared__ float tile[32][33];

    const int b = blockIdx.z;
    const float* sb = src + (size_t)b * CC * HW;
    float* db = g_featT + (size_t)b * HW * CC;

    // read: rows = channels (y), cols = hw (x). Coalesced along hw.
    int x = blockIdx.x * 32 + threadIdx.x;   // hw
    int y = blockIdx.y * 32 + threadIdx.y;   // c
#pragma unroll
    for (int j = 0; j < 32; j += 8) {
        tile[threadIdx.y + j][threadIdx.x] = sb[(size_t)(y + j) * HW + x];
    }
    __syncthreads();

    // write: rows = hw (y2), cols = channels (x2). Coalesced along c.
    int x2 = blockIdx.y * 32 + threadIdx.x;  // c
    int y2 = blockIdx.x * 32 + threadIdx.y;  // hw
#pragma unroll
    for (int j = 0; j < 32; j += 8) {
        db[(size_t)(y2 + j) * CC + x2] = tile[threadIdx.x][threadIdx.y + j];
    }
}

// ---------------------------------------------------------------------------
// Kernel 2: one warp per point. Each lane handles 4 channels (float4).
// Corner reads are contiguous 512B per corner (32 lanes x 16B).
// ---------------------------------------------------------------------------
__global__ __launch_bounds__(256) void gather_kernel(
    const float* __restrict__ tk_codes,   // [B, P, 2]
    float* __restrict__ out)              // [B, P, C]
{
    const int gwarp = (blockIdx.x * blockDim.x + threadIdx.x) >> 5;
    const int lane = threadIdx.x & 31;
    if (gwarp >= BB * PP) return;

    // Contiguous point index: gwarp = b*P + i
    const float2 pt = ((const float2*)tk_codes)[gwarp];
    const float x = pt.x;
    const float y = pt.y;

    const bool inb = (x >= 0.0f) & (y >= 0.0f) &
                     (x <= (float)(WW - 1)) & (y <= (float)(HH - 1));

    const float fx = floorf(x), cx = ceilf(x);
    const float fy = floorf(y), cy = ceilf(y);

    const float corner_x[4] = {fx, fx, cx, cx};
    const float corner_y[4] = {fy, cy, fy, cy};

    float w4[4];
    int idx4[4];
    float denom = 0.0f;
#pragma unroll
    for (int k = 0; k < 4; k++) {
        int gx = ((int)corner_x[k]) % WW;   // C-style %: sign of dividend == jnp.fmod(int32)
        int gy = ((int)corner_y[k]) % HH;
        gx = max(gx, 0);
        gy = max(gy, 0);
        const float dx = x - (float)gx;
        const float dy = y - (float)gy;
        const float dist_inv = 1.0f / (sqrtf(dx * dx + dy * dy) + 1e-10f);
        const float wk = inb ? dist_inv : 0.0f;
        w4[k] = wk;
        denom += wk;
        idx4[k] = gy * WW + gx;
    }
    if (denom == 0.0f) denom = 1.0f;
#pragma unroll
    for (int k = 0; k < 4; k++) w4[k] /= denom;

    const int b = gwarp >> 15;             // P = 32768
    const float4* __restrict__ baseT =
        (const float4*)g_featT + (size_t)b * HW * (CC / 4);

    float4 acc = make_float4(0.0f, 0.0f, 0.0f, 0.0f);
#pragma unroll
    for (int k = 0; k < 4; k++) {
        const float4 v = baseT[(size_t)idx4[k] * (CC / 4) + lane];
        acc.x += w4[k] * v.x;
        acc.y += w4[k] * v.y;
        acc.z += w4[k] * v.z;
        acc.w += w4[k] * v.w;
    }

    float4* __restrict__ o4 = (float4*)out;
    o4[(size_t)gwarp * (CC / 4) + lane] = acc;
}

// ---------------------------------------------------------------------------
extern "C" void kernel_launch(void* const* d_in, const int* in_sizes, int n_in,
                              void* d_out, int out_size) {
    const float* tk_codes = (const float*)d_in[0];   // [B, P, 2] float32
    const float* feat     = (const float*)d_in[1];   // [B, C, H, W] float32
    float* out            = (float*)d_out;           // [B, P, C] float32

    (void)in_sizes; (void)n_in; (void)out_size;

    dim3 tgrid(HW / 32, CC / 32, BB);
    dim3 tblock(32, 8);
    transpose_kernel<<<tgrid, tblock>>>(feat);

    const int total_warps = BB * PP;             // 262144 points, 1 warp each
    const int threads = 256;                     // 8 warps/block
    const int blocks = (total_warps * 32) / threads;
    gather_kernel<<<blocks, threads>>>(tk_codes, out);
}

// round 2
// speedup vs baseline: 1.1949x; 1.1949x over previous
#include <cuda_runtime.h>
#include <cstdint>

// Problem constants (fixed by the reference)
#define BB 8
#define CC 128
#define HH 128
#define WW 128
#define PP 32768
#define HW (HH * WW)

// Scratch: feat_grid transposed to [B, H*W, C] (channels-last). 67 MB.
__device__ float g_featT[BB * HW * CC];

// ---------------------------------------------------------------------------
// Kernel 1: tiled transpose per batch:  src[C][HW] -> dst[HW][C]
// grid: (HW/32, C/32, B), block: (32, 8)
// ---------------------------------------------------------------------------
__global__ void transpose_kernel(const float* __restrict__ src) {
    __shared__ float tile[32][33];

    const int b = blockIdx.z;
    const float* sb = src + (size_t)b * CC * HW;
    float* db = g_featT + (size_t)b * HW * CC;

    // read: rows = channels (y), cols = hw (x). Coalesced along hw.
    int x = blockIdx.x * 32 + threadIdx.x;   // hw
    int y = blockIdx.y * 32 + threadIdx.y;   // c
#pragma unroll
    for (int j = 0; j < 32; j += 8) {
        // streaming read: feat_grid is never re-read
        tile[threadIdx.y + j][threadIdx.x] = __ldcs(&sb[(size_t)(y + j) * HW + x]);
    }
    __syncthreads();

    // write: rows = hw (y2), cols = channels (x2). Coalesced along c.
    int x2 = blockIdx.y * 32 + threadIdx.x;  // c
    int y2 = blockIdx.x * 32 + threadIdx.y;  // hw
#pragma unroll
    for (int j = 0; j < 32; j += 8) {
        db[(size_t)(y2 + j) * CC + x2] = tile[threadIdx.x][threadIdx.y + j];
    }
}

// ---------------------------------------------------------------------------
// Kernel 2: one warp per point, lane handles 4 channels (float4).
// Corner weight math computed ONCE per warp: lane computes corner (lane&3),
// denom via shfl butterfly, then width-4 shfl broadcast of idx/weight.
// ---------------------------------------------------------------------------
__global__ __launch_bounds__(256) void gather_kernel(
    const float* __restrict__ tk_codes,   // [B, P, 2]
    float* __restrict__ out)              // [B, P, C]
{
    const unsigned FULL = 0xffffffffu;
    const int gwarp = (blockIdx.x * blockDim.x + threadIdx.x) >> 5;
    const int lane = threadIdx.x & 31;

    // all lanes load the same 8B -> single broadcast wavefront
    const float2 pt = __ldg(((const float2*)tk_codes) + gwarp);
    const float x = pt.x;
    const float y = pt.y;

    const bool inb = (x >= 0.0f) & (y >= 0.0f) &
                     (x <= (float)(WW - 1)) & (y <= (float)(HH - 1));

    // this lane's corner: bit1 of k -> ceil(x), bit0 of k -> ceil(y)
    // (reference order: (fx,fy),(fx,cy),(cx,fy),(cx,cy))
    const int k = lane & 3;
    const float cxk = (k & 2) ? ceilf(x) : floorf(x);
    const float cyk = (k & 1) ? ceilf(y) : floorf(y);

    int gx = ((int)cxk) % WW;   // C-style %: matches jnp.fmod on int32
    int gy = ((int)cyk) % HH;
    gx = max(gx, 0);
    gy = max(gy, 0);

    const float dx = x - (float)gx;
    const float dy = y - (float)gy;
    float w = inb ? (1.0f / (sqrtf(dx * dx + dy * dy) + 1e-10f)) : 0.0f;

    // denom = sum of the 4 corner weights (butterfly within the 4-group)
    float d = w + __shfl_xor_sync(FULL, w, 1);
    d += __shfl_xor_sync(FULL, d, 2);
    if (d == 0.0f) d = 1.0f;
    w /= d;

    const int idx = (gy << 7) + gx;

    // broadcast corner data to all lanes (every 4-group holds identical values)
    const float w0 = __shfl_sync(FULL, w, 0, 4);
    const float w1 = __shfl_sync(FULL, w, 1, 4);
    const float w2 = __shfl_sync(FULL, w, 2, 4);
    const float w3 = __shfl_sync(FULL, w, 3, 4);
    const int   i0 = __shfl_sync(FULL, idx, 0, 4);
    const int   i1 = __shfl_sync(FULL, idx, 1, 4);
    const int   i2 = __shfl_sync(FULL, idx, 2, 4);
    const int   i3 = __shfl_sync(FULL, idx, 3, 4);

    const int b = gwarp >> 15;             // P = 32768
    const float4* __restrict__ baseT =
        (const float4*)g_featT + (size_t)b * (HW * (CC / 4));

    const float4 v0 = baseT[(size_t)i0 * (CC / 4) + lane];
    const float4 v1 = baseT[(size_t)i1 * (CC / 4) + lane];
    const float4 v2 = baseT[(size_t)i2 * (CC / 4) + lane];
    const float4 v3 = baseT[(size_t)i3 * (CC / 4) + lane];

    float4 acc;
    acc.x = w0 * v0.x + w1 * v1.x + w2 * v2.x + w3 * v3.x;
    acc.y = w0 * v0.y + w1 * v1.y + w2 * v2.y + w3 * v3.y;
    acc.z = w0 * v0.z + w1 * v1.z + w2 * v2.z + w3 * v3.z;
    acc.w = w0 * v0.w + w1 * v1.w + w2 * v2.w + w3 * v3.w;

    // streaming store: output never re-read; keep featT resident in L2
    __stcs(((float4*)out) + (size_t)gwarp * (CC / 4) + lane, acc);
}

// ---------------------------------------------------------------------------
extern "C" void kernel_launch(void* const* d_in, const int* in_sizes, int n_in,
                              void* d_out, int out_size) {
    const float* tk_codes = (const float*)d_in[0];   // [B, P, 2] float32
    const float* feat     = (const float*)d_in[1];   // [B, C, H, W] float32
    float* out            = (float*)d_out;           // [B, P, C] float32

    (void)in_sizes; (void)n_in; (void)out_size;

    dim3 tgrid(HW / 32, CC / 32, BB);
    dim3 tblock(32, 8);
    transpose_kernel<<<tgrid, tblock>>>(feat);

    const int total_warps = BB * PP;             // 262144 points, 1 warp each
    const int threads = 256;                     // 8 warps/block
    const int blocks = (total_warps * 32) / threads;
    gather_kernel<<<blocks, threads>>>(tk_codes, out);
}

// round 3
// speedup vs baseline: 1.3432x; 1.1241x over previous
#include <cuda_runtime.h>
#include <cstdint>

// Problem constants (fixed by the reference)
#define BB 8
#define CC 128
#define HH 128
#define WW 128
#define PP 32768
#define HW (HH * WW)

// Scratch: feat_grid transposed to [B, H*W, C] (channels-last). 67 MB.
__device__ float g_featT[BB * HW * CC];

// ---------------------------------------------------------------------------
// Kernel 1: tiled transpose per batch:  src[C][HW] -> dst[HW][C]
// grid: (HW/32, C/32, B), block: (32, 8)
// ---------------------------------------------------------------------------
__global__ void transpose_kernel(const float* __restrict__ src) {
    __shared__ float tile[32][33];

    const int b = blockIdx.z;
    const float* sb = src + (size_t)b * CC * HW;
    float* db = g_featT + (size_t)b * HW * CC;

    int x = blockIdx.x * 32 + threadIdx.x;   // hw
    int y = blockIdx.y * 32 + threadIdx.y;   // c
#pragma unroll
    for (int j = 0; j < 32; j += 8) {
        tile[threadIdx.y + j][threadIdx.x] = __ldcs(&sb[(size_t)(y + j) * HW + x]);
    }
    __syncthreads();

    int x2 = blockIdx.y * 32 + threadIdx.x;  // c
    int y2 = blockIdx.x * 32 + threadIdx.y;  // hw
#pragma unroll
    for (int j = 0; j < 32; j += 8) {
        db[(size_t)(y2 + j) * CC + x2] = tile[threadIdx.x][threadIdx.y + j];
    }
}

// ---------------------------------------------------------------------------
// Kernel 2: TWO points per warp. Corner math runs once per warp for both
// points (lanes 0-3 = corners of point A, lanes 4-7 = corners of point B).
// 8 independent LDG.128 per warp (high MLP), 1KB contiguous store.
// ---------------------------------------------------------------------------
__global__ __launch_bounds__(256) void gather_kernel(
    const float* __restrict__ tk_codes,   // [B, P, 2]
    float* __restrict__ out)              // [B, P, C]
{
    const unsigned FULL = 0xffffffffu;
    const int pair = (blockIdx.x * blockDim.x + threadIdx.x) >> 5;  // point pair
    const int lane = threadIdx.x & 31;

    // one 16B broadcast load carries both points: (xA, yA, xB, yB)
    const float4 pts = __ldg(((const float4*)tk_codes) + pair);

    // this lane's point (j) and corner (k)
    const int j = (lane >> 2) & 1;
    const int k = lane & 3;
    const float x = j ? pts.z : pts.x;
    const float y = j ? pts.w : pts.y;

    const bool inb = (x >= 0.0f) & (y >= 0.0f) &
                     (x <= (float)(WW - 1)) & (y <= (float)(HH - 1));

    // corner order: (fx,fy),(fx,cy),(cx,fy),(cx,cy)  -> k bit1 = ceil x, bit0 = ceil y
    const float cxk = (k & 2) ? ceilf(x) : floorf(x);
    const float cyk = (k & 1) ? ceilf(y) : floorf(y);

    int gx = ((int)cxk) % WW;   // C-style %: matches jnp.fmod on int32
    int gy = ((int)cyk) % HH;
    gx = max(gx, 0);
    gy = max(gy, 0);

    const float dx = x - (float)gx;
    const float dy = y - (float)gy;
    float w = inb ? __fdividef(1.0f, sqrtf(dx * dx + dy * dy) + 1e-10f) : 0.0f;

    // per-4-group butterfly: sums the 4 corner weights of this lane's point
    float d = w + __shfl_xor_sync(FULL, w, 1);
    d += __shfl_xor_sync(FULL, d, 2);
    if (d == 0.0f) d = 1.0f;
    w *= __fdividef(1.0f, d);

    const int idx = (gy << 7) + gx;

    // width-8 broadcasts: lanes 0-3 of each 8-group hold point A, 4-7 point B
    const float wA0 = __shfl_sync(FULL, w, 0, 8);
    const float wA1 = __shfl_sync(FULL, w, 1, 8);
    const float wA2 = __shfl_sync(FULL, w, 2, 8);
    const float wA3 = __shfl_sync(FULL, w, 3, 8);
    const float wB0 = __shfl_sync(FULL, w, 4, 8);
    const float wB1 = __shfl_sync(FULL, w, 5, 8);
    const float wB2 = __shfl_sync(FULL, w, 6, 8);
    const float wB3 = __shfl_sync(FULL, w, 7, 8);
    const int iA0 = __shfl_sync(FULL, idx, 0, 8);
    const int iA1 = __shfl_sync(FULL, idx, 1, 8);
    const int iA2 = __shfl_sync(FULL, idx, 2, 8);
    const int iA3 = __shfl_sync(FULL, idx, 3, 8);
    const int iB0 = __shfl_sync(FULL, idx, 4, 8);
    const int iB1 = __shfl_sync(FULL, idx, 5, 8);
    const int iB2 = __shfl_sync(FULL, idx, 6, 8);
    const int iB3 = __shfl_sync(FULL, idx, 7, 8);

    const int pA = pair * 2;                 // both points in same batch (P even)
    const int b = pA >> 15;                  // P = 32768
    const float4* __restrict__ baseT =
        (const float4*)g_featT + (size_t)b * (HW * (CC / 4));

    // 8 independent 16B loads per lane-slot (512B/warp each, contiguous)
    const float4 vA0 = baseT[(size_t)iA0 * (CC / 4) + lane];
    const float4 vA1 = baseT[(size_t)iA1 * (CC / 4) + lane];
    const float4 vA2 = baseT[(size_t)iA2 * (CC / 4) + lane];
    const float4 vA3 = baseT[(size_t)iA3 * (CC / 4) + lane];
    const float4 vB0 = baseT[(size_t)iB0 * (CC / 4) + lane];
    const float4 vB1 = baseT[(size_t)iB1 * (CC / 4) + lane];
    const float4 vB2 = baseT[(size_t)iB2 * (CC / 4) + lane];
    const float4 vB3 = baseT[(size_t)iB3 * (CC / 4) + lane];

    float4 accA, accB;
    accA.x = wA0 * vA0.x + wA1 * vA1.x + wA2 * vA2.x + wA3 * vA3.x;
    accA.y = wA0 * vA0.y + wA1 * vA1.y + wA2 * vA2.y + wA3 * vA3.y;
    accA.z = wA0 * vA0.z + wA1 * vA1.z + wA2 * vA2.z + wA3 * vA3.z;
    accA.w = wA0 * vA0.w + wA1 * vA1.w + wA2 * vA2.w + wA3 * vA3.w;
    accB.x = wB0 * vB0.x + wB1 * vB1.x + wB2 * vB2.x + wB3 * vB3.x;
    accB.y = wB0 * vB0.y + wB1 * vB1.y + wB2 * vB2.y + wB3 * vB3.y;
    accB.z = wB0 * vB0.z + wB1 * vB1.z + wB2 * vB2.z + wB3 * vB3.z;
    accB.w = wB0 * vB0.w + wB1 * vB1.w + wB2 * vB2.w + wB3 * vB3.w;

    // streaming stores: 1KB contiguous per warp (pA, pA+1 adjacent rows)
    float4* __restrict__ o4 = (float4*)out;
    __stcs(o4 + (size_t)pA * (CC / 4) + lane, accA);
    __stcs(o4 + (size_t)(pA + 1) * (CC / 4) + lane, accB);
}

// ---------------------------------------------------------------------------
extern "C" void kernel_launch(void* const* d_in, const int* in_sizes, int n_in,
                              void* d_out, int out_size) {
    const float* tk_codes = (const float*)d_in[0];   // [B, P, 2] float32
    const float* feat     = (const float*)d_in[1];   // [B, C, H, W] float32
    float* out            = (float*)d_out;           // [B, P, C] float32

    (void)in_sizes; (void)n_in; (void)out_size;

    dim3 tgrid(HW / 32, CC / 32, BB);
    dim3 tblock(32, 8);
    transpose_kernel<<<tgrid, tblock>>>(feat);

    const int total_pairs = BB * PP / 2;         // 131072 pairs, 1 warp each
    const int threads = 256;                     // 8 warps/block
    const int blocks = (total_pairs * 32) / threads;
    gather_kernel<<<blocks, threads>>>(tk_codes, out);
}

// round 4
// speedup vs baseline: 1.7470x; 1.3006x over previous
#include <cuda_runtime.h>
#include <cuda_fp16.h>
#include <cstdint>

// Problem constants (fixed by the reference)
#define BB 8
#define CC 128
#define HH 128
#define WW 128
#define PP 32768
#define HW (HH * WW)

// Scratch: feat_grid transposed to [B, H*W, C] channels-last, fp16. 33.5 MB.
__device__ __half g_featT[BB * HW * CC];

// ---------------------------------------------------------------------------
// Kernel 1: tiled transpose + f32->fp16:  src[C][HW] -> dstT[HW][C] (half)
// grid: (HW/32, C/32, B), block: (32, 8). 32x32 tile.
// ---------------------------------------------------------------------------
__global__ void transpose_kernel(const float* __restrict__ src) {
    __shared__ float tile[32][33];

    const int b = blockIdx.z;
    const float* sb = src + (size_t)b * CC * HW;
    __half2* db = (__half2*)(g_featT + (size_t)b * HW * CC);

    const int tx = threadIdx.x, ty = threadIdx.y;

    // read: rows = channels (y), cols = hw (x). Coalesced 128B along hw.
    int x = blockIdx.x * 32 + tx;            // hw
    int y = blockIdx.y * 32 + ty;            // c
#pragma unroll
    for (int j = 0; j < 32; j += 8) {
        tile[ty + j][tx] = __ldcs(&sb[(size_t)(y + j) * HW + x]);
    }
    __syncthreads();

    // write: each lane packs 2 channels into one half2.
    // lanes 0-15 -> hw row (2*ty), lanes 16-31 -> hw row (2*ty+1).
    const int cpair = tx & 15;                       // half2 index within 32-ch chunk
    const int rsub = tx >> 4;                        // 0/1: which of the 2 rows
    const int hw_base = blockIdx.x * 32;             // this tile's hw start
    const int c2_base = blockIdx.y * 16;             // half2 column base (32ch/2)
#pragma unroll
    for (int j = 0; j < 32; j += 16) {
        const int row = (ty << 1) + rsub + j;        // local hw row 0..31
        const float lo = tile[2 * cpair][row];
        const float hi = tile[2 * cpair + 1][row];
        db[(size_t)(hw_base + row) * (CC / 2) + c2_base + cpair] =
            __floats2half2_rn(lo, hi);
    }
}

// ---------------------------------------------------------------------------
// Kernel 2: TWO points per warp, fp16 corner reads (8B/lane), f32 math/out.
// ---------------------------------------------------------------------------
__global__ __launch_bounds__(256) void gather_kernel(
    const float* __restrict__ tk_codes,   // [B, P, 2]
    float* __restrict__ out)              // [B, P, C]
{
    const unsigned FULL = 0xffffffffu;
    const int pair = (blockIdx.x * blockDim.x + threadIdx.x) >> 5;  // point pair
    const int lane = threadIdx.x & 31;

    // one 16B broadcast load carries both points: (xA, yA, xB, yB)
    const float4 pts = __ldg(((const float4*)tk_codes) + pair);

    const int j = (lane >> 2) & 1;
    const int k = lane & 3;
    const float x = j ? pts.z : pts.x;
    const float y = j ? pts.w : pts.y;

    const bool inb = (x >= 0.0f) & (y >= 0.0f) &
                     (x <= (float)(WW - 1)) & (y <= (float)(HH - 1));

    // corner order: (fx,fy),(fx,cy),(cx,fy),(cx,cy)
    const float cxk = (k & 2) ? ceilf(x) : floorf(x);
    const float cyk = (k & 1) ? ceilf(y) : floorf(y);

    int gx = ((int)cxk) % WW;   // C-style %: matches jnp.fmod on int32
    int gy = ((int)cyk) % HH;
    gx = max(gx, 0);
    gy = max(gy, 0);

    const float dx = x - (float)gx;
    const float dy = y - (float)gy;
    float w = inb ? __fdividef(1.0f, sqrtf(dx * dx + dy * dy) + 1e-10f) : 0.0f;

    float d = w + __shfl_xor_sync(FULL, w, 1);
    d += __shfl_xor_sync(FULL, d, 2);
    if (d == 0.0f) d = 1.0f;
    w *= __fdividef(1.0f, d);

    const int idx = (gy << 7) + gx;

    const float wA0 = __shfl_sync(FULL, w, 0, 8);
    const float wA1 = __shfl_sync(FULL, w, 1, 8);
    const float wA2 = __shfl_sync(FULL, w, 2, 8);
    const float wA3 = __shfl_sync(FULL, w, 3, 8);
    const float wB0 = __shfl_sync(FULL, w, 4, 8);
    const float wB1 = __shfl_sync(FULL, w, 5, 8);
    const float wB2 = __shfl_sync(FULL, w, 6, 8);
    const float wB3 = __shfl_sync(FULL, w, 7, 8);
    const int iA0 = __shfl_sync(FULL, idx, 0, 8);
    const int iA1 = __shfl_sync(FULL, idx, 1, 8);
    const int iA2 = __shfl_sync(FULL, idx, 2, 8);
    const int iA3 = __shfl_sync(FULL, idx, 3, 8);
    const int iB0 = __shfl_sync(FULL, idx, 4, 8);
    const int iB1 = __shfl_sync(FULL, idx, 5, 8);
    const int iB2 = __shfl_sync(FULL, idx, 6, 8);
    const int iB3 = __shfl_sync(FULL, idx, 7, 8);

    const int pA = pair * 2;                 // both points in same batch (P even)
    const int b = pA >> 15;                  // P = 32768
    // row = 128 ch * 2B = 256B = 32 uint2; lane covers channels [4*lane, 4*lane+4)
    const uint2* __restrict__ baseT =
        (const uint2*)(g_featT + (size_t)b * HW * CC);

    const uint2 rA0 = baseT[(size_t)iA0 * 32 + lane];
    const uint2 rA1 = baseT[(size_t)iA1 * 32 + lane];
    const uint2 rA2 = baseT[(size_t)iA2 * 32 + lane];
    const uint2 rA3 = baseT[(size_t)iA3 * 32 + lane];
    const uint2 rB0 = baseT[(size_t)iB0 * 32 + lane];
    const uint2 rB1 = baseT[(size_t)iB1 * 32 + lane];
    const uint2 rB2 = baseT[(size_t)iB2 * 32 + lane];
    const uint2 rB3 = baseT[(size_t)iB3 * 32 + lane];

    float4 accA = make_float4(0.f, 0.f, 0.f, 0.f);
    float4 accB = make_float4(0.f, 0.f, 0.f, 0.f);

#define ACC(acc, r, wk)                                                  \
    {                                                                    \
        const float2 f0 = __half22float2(*(const __half2*)&(r).x);       \
        const float2 f1 = __half22float2(*(const __half2*)&(r).y);       \
        (acc).x = fmaf((wk), f0.x, (acc).x);                             \
        (acc).y = fmaf((wk), f0.y, (acc).y);                             \
        (acc).z = fmaf((wk), f1.x, (acc).z);                             \
        (acc).w = fmaf((wk), f1.y, (acc).w);                             \
    }

    ACC(accA, rA0, wA0); ACC(accA, rA1, wA1);
    ACC(accA, rA2, wA2); ACC(accA, rA3, wA3);
    ACC(accB, rB0, wB0); ACC(accB, rB1, wB1);
    ACC(accB, rB2, wB2); ACC(accB, rB3, wB3);
#undef ACC

    // streaming stores: 1KB contiguous per warp
    float4* __restrict__ o4 = (float4*)out;
    __stcs(o4 + (size_t)pA * 32 + lane, accA);
    __stcs(o4 + (size_t)(pA + 1) * 32 + lane, accB);
}

// ---------------------------------------------------------------------------
extern "C" void kernel_launch(void* const* d_in, const int* in_sizes, int n_in,
                              void* d_out, int out_size) {
    const float* tk_codes = (const float*)d_in[0];   // [B, P, 2] float32
    const float* feat     = (const float*)d_in[1];   // [B, C, H, W] float32
    float* out            = (float*)d_out;           // [B, P, C] float32

    (void)in_sizes; (void)n_in; (void)out_size;

    dim3 tgrid(HW / 32, CC / 32, BB);
    dim3 tblock(32, 8);
    transpose_kernel<<<tgrid, tblock>>>(feat);

    const int total_pairs = BB * PP / 2;         // 131072 pairs, 1 warp each
    const int threads = 256;                     // 8 warps/block
    const int blocks = (total_pairs * 32) / threads;
    gather_kernel<<<blocks, threads>>>(tk_codes, out);
}

// round 6
// speedup vs baseline: 1.7927x; 1.0262x over previous
#include <cuda_runtime.h>
#include <cuda_fp16.h>
#include <cstdint>

// Problem constants (fixed by the reference)
#define BB 8
#define CC 128
#define HH 128
#define WW 128
#define PP 32768
#define HW (HH * WW)

// Scratch: feat_grid transposed to [B, H*W, C] channels-last, fp16. 33.5 MB.
__device__ __half g_featT[BB * HW * CC];

// bit-cast helpers (the named intrinsics don't exist in cuda_fp16.h)
static __device__ __forceinline__ unsigned h2_to_u32(__half2 h) {
    return *reinterpret_cast<unsigned*>(&h);
}
static __device__ __forceinline__ __half2 u32_to_h2(unsigned u) {
    return *reinterpret_cast<__half2*>(&u);
}

// ---------------------------------------------------------------------------
// Kernel 1: tiled transpose + f32->fp16:  src[C][HW] -> dstT[HW][C] (half)
// grid: (HW/32, C/32, B), block: (32, 8). 32x32 tile.
// ---------------------------------------------------------------------------
__global__ void transpose_kernel(const float* __restrict__ src) {
    __shared__ float tile[32][33];

    const int b = blockIdx.z;
    const float* sb = src + (size_t)b * CC * HW;
    __half2* db = (__half2*)(g_featT + (size_t)b * HW * CC);

    const int tx = threadIdx.x, ty = threadIdx.y;

    // read: rows = channels (y), cols = hw (x). Coalesced 128B along hw.
    int x = blockIdx.x * 32 + tx;            // hw
    int y = blockIdx.y * 32 + ty;            // c
#pragma unroll
    for (int j = 0; j < 32; j += 8) {
        tile[ty + j][tx] = __ldcs(&sb[(size_t)(y + j) * HW + x]);
    }
    __syncthreads();

    // write: each lane packs 2 channels into one half2.
    const int cpair = tx & 15;                       // half2 index within 32-ch chunk
    const int rsub = tx >> 4;                        // 0/1: which of the 2 rows
    const int hw_base = blockIdx.x * 32;             // this tile's hw start
    const int c2_base = blockIdx.y * 16;             // half2 column base (32ch/2)
#pragma unroll
    for (int j = 0; j < 32; j += 16) {
        const int row = (ty << 1) + rsub + j;        // local hw row 0..31
        const float lo = tile[2 * cpair][row];
        const float hi = tile[2 * cpair + 1][row];
        db[(size_t)(hw_base + row) * (CC / 2) + c2_base + cpair] =
            __floats2half2_rn(lo, hi);
    }
}

// ---------------------------------------------------------------------------
// Kernel 2: TWO points per warp, fp16 corner reads + HFMA2 accumulation.
// ---------------------------------------------------------------------------
__global__ __launch_bounds__(256) void gather_kernel(
    const float* __restrict__ tk_codes,   // [B, P, 2]
    float* __restrict__ out)              // [B, P, C]
{
    const unsigned FULL = 0xffffffffu;
    const int pair = (blockIdx.x * blockDim.x + threadIdx.x) >> 5;  // point pair
    const int lane = threadIdx.x & 31;

    // one 16B broadcast load carries both points: (xA, yA, xB, yB)
    const float4 pts = __ldg(((const float4*)tk_codes) + pair);

    const int j = (lane >> 2) & 1;
    const int k = lane & 3;
    const float x = j ? pts.z : pts.x;
    const float y = j ? pts.w : pts.y;

    const bool inb = (x >= 0.0f) & (y >= 0.0f) &
                     (x <= (float)(WW - 1)) & (y <= (float)(HH - 1));

    // corner order: (fx,fy),(fx,cy),(cx,fy),(cx,cy)
    const float cxk = (k & 2) ? ceilf(x) : floorf(x);
    const float cyk = (k & 1) ? ceilf(y) : floorf(y);

    int gx = ((int)cxk) % WW;   // C-style %: matches jnp.fmod on int32
    int gy = ((int)cyk) % HH;
    gx = max(gx, 0);
    gy = max(gy, 0);

    const float dx = x - (float)gx;
    const float dy = y - (float)gy;
    float w = inb ? __fdividef(1.0f, sqrtf(dx * dx + dy * dy) + 1e-10f) : 0.0f;

    float d = w + __shfl_xor_sync(FULL, w, 1);
    d += __shfl_xor_sync(FULL, d, 2);
    if (d == 0.0f) d = 1.0f;
    w *= __fdividef(1.0f, d);           // normalized weight in [0,1]

    const int idx = (gy << 7) + gx;

    // duplicate normalized weight into a half2 BEFORE broadcast (1 cvt, SIMT)
    const unsigned hw2 = h2_to_u32(__float2half2_rn(w));

    // width-8 broadcasts: lanes 0-3 hold point A corners, 4-7 point B
    const __half2 wA0 = u32_to_h2(__shfl_sync(FULL, hw2, 0, 8));
    const __half2 wA1 = u32_to_h2(__shfl_sync(FULL, hw2, 1, 8));
    const __half2 wA2 = u32_to_h2(__shfl_sync(FULL, hw2, 2, 8));
    const __half2 wA3 = u32_to_h2(__shfl_sync(FULL, hw2, 3, 8));
    const __half2 wB0 = u32_to_h2(__shfl_sync(FULL, hw2, 4, 8));
    const __half2 wB1 = u32_to_h2(__shfl_sync(FULL, hw2, 5, 8));
    const __half2 wB2 = u32_to_h2(__shfl_sync(FULL, hw2, 6, 8));
    const __half2 wB3 = u32_to_h2(__shfl_sync(FULL, hw2, 7, 8));
    const int iA0 = __shfl_sync(FULL, idx, 0, 8);
    const int iA1 = __shfl_sync(FULL, idx, 1, 8);
    const int iA2 = __shfl_sync(FULL, idx, 2, 8);
    const int iA3 = __shfl_sync(FULL, idx, 3, 8);
    const int iB0 = __shfl_sync(FULL, idx, 4, 8);
    const int iB1 = __shfl_sync(FULL, idx, 5, 8);
    const int iB2 = __shfl_sync(FULL, idx, 6, 8);
    const int iB3 = __shfl_sync(FULL, idx, 7, 8);

    const int pA = pair * 2;                 // both points in same batch (P even)
    const int b = pA >> 15;                  // P = 32768
    // row = 128 ch * 2B = 256B = 32 uint2; lane covers channels [4*lane, 4*lane+4)
    const uint2* __restrict__ baseT =
        (const uint2*)(g_featT + (size_t)b * HW * CC);

    const uint2 rA0 = baseT[(size_t)iA0 * 32 + lane];
    const uint2 rA1 = baseT[(size_t)iA1 * 32 + lane];
    const uint2 rA2 = baseT[(size_t)iA2 * 32 + lane];
    const uint2 rA3 = baseT[(size_t)iA3 * 32 + lane];
    const uint2 rB0 = baseT[(size_t)iB0 * 32 + lane];
    const uint2 rB1 = baseT[(size_t)iB1 * 32 + lane];
    const uint2 rB2 = baseT[(size_t)iB2 * 32 + lane];
    const uint2 rB3 = baseT[(size_t)iB3 * 32 + lane];

#define H2LO(r) (u32_to_h2((r).x))
#define H2HI(r) (u32_to_h2((r).y))

    // fp16 accumulation: 2 HFMA2 per corner (HMUL2 for the first)
    __half2 aA0 = __hmul2(wA0, H2LO(rA0));
    __half2 aA1 = __hmul2(wA0, H2HI(rA0));
    aA0 = __hfma2(wA1, H2LO(rA1), aA0);
    aA1 = __hfma2(wA1, H2HI(rA1), aA1);
    aA0 = __hfma2(wA2, H2LO(rA2), aA0);
    aA1 = __hfma2(wA2, H2HI(rA2), aA1);
    aA0 = __hfma2(wA3, H2LO(rA3), aA0);
    aA1 = __hfma2(wA3, H2HI(rA3), aA1);

    __half2 aB0 = __hmul2(wB0, H2LO(rB0));
    __half2 aB1 = __hmul2(wB0, H2HI(rB0));
    aB0 = __hfma2(wB1, H2LO(rB1), aB0);
    aB1 = __hfma2(wB1, H2HI(rB1), aB1);
    aB0 = __hfma2(wB2, H2LO(rB2), aB0);
    aB1 = __hfma2(wB2, H2HI(rB2), aB1);
    aB0 = __hfma2(wB3, H2LO(rB3), aB0);
    aB1 = __hfma2(wB3, H2HI(rB3), aB1);
#undef H2LO
#undef H2HI

    float4 accA, accB;
    {
        const float2 f0 = __half22float2(aA0);
        const float2 f1 = __half22float2(aA1);
        accA = make_float4(f0.x, f0.y, f1.x, f1.y);
        const float2 g0 = __half22float2(aB0);
        const float2 g1 = __half22float2(aB1);
        accB = make_float4(g0.x, g0.y, g1.x, g1.y);
    }

    // streaming stores: 1KB contiguous per warp
    float4* __restrict__ o4 = (float4*)out;
    __stcs(o4 + (size_t)pA * 32 + lane, accA);
    __stcs(o4 + (size_t)(pA + 1) * 32 + lane, accB);
}

// ---------------------------------------------------------------------------
extern "C" void kernel_launch(void* const* d_in, const int* in_sizes, int n_in,
                              void* d_out, int out_size) {
    const float* tk_codes = (const float*)d_in[0];   // [B, P, 2] float32
    const float* feat     = (const float*)d_in[1];   // [B, C, H, W] float32
    float* out            = (float*)d_out;           // [B, P, C] float32

    (void)in_sizes; (void)n_in; (void)out_size;

    dim3 tgrid(HW / 32, CC / 32, BB);
    dim3 tblock(32, 8);
    transpose_kernel<<<tgrid, tblock>>>(feat);

    const int total_pairs = BB * PP / 2;         // 131072 pairs, 1 warp each
    const int threads = 256;                     // 8 warps/block
    const int blocks = (total_pairs * 32) / threads;
    gather_kernel<<<blocks, threads>>>(tk_codes, out);
}

// round 7
// speedup vs baseline: 1.8649x; 1.0403x over previous
#include <cuda_runtime.h>
#include <cuda_fp16.h>
#include <cstdint>

// Problem constants (fixed by the reference)
#define BB 8
#define CC 128
#define HH 128
#define WW 128
#define PP 32768
#define HW (HH * WW)

// Scratch: feat_grid transposed to [B, H*W, C] channels-last, fp16. 33.5 MB.
__device__ __half g_featT[BB * HW * CC];

// bit-cast helpers
static __device__ __forceinline__ unsigned h2_to_u32(__half2 h) {
    return *reinterpret_cast<unsigned*>(&h);
}
static __device__ __forceinline__ __half2 u32_to_h2(unsigned u) {
    return *reinterpret_cast<__half2*>(&u);
}

// ---------------------------------------------------------------------------
// Kernel 1: tiled transpose + f32->fp16:  src[C][HW] -> dstT[HW][C] (half)
// grid: (HW/32, C/32, B), block: (32, 8). 32x32 tile.
// ---------------------------------------------------------------------------
__global__ void transpose_kernel(const float* __restrict__ src) {
    __shared__ float tile[32][33];

    const int b = blockIdx.z;
    const float* sb = src + (size_t)b * CC * HW;
    __half2* db = (__half2*)(g_featT + (size_t)b * HW * CC);

    const int tx = threadIdx.x, ty = threadIdx.y;

    int x = blockIdx.x * 32 + tx;            // hw
    int y = blockIdx.y * 32 + ty;            // c
#pragma unroll
    for (int j = 0; j < 32; j += 8) {
        tile[ty + j][tx] = __ldcs(&sb[(size_t)(y + j) * HW + x]);
    }
    __syncthreads();

    const int cpair = tx & 15;
    const int rsub = tx >> 4;
    const int hw_base = blockIdx.x * 32;
    const int c2_base = blockIdx.y * 16;
#pragma unroll
    for (int j = 0; j < 32; j += 16) {
        const int row = (ty << 1) + rsub + j;
        const float lo = tile[2 * cpair][row];
        const float hi = tile[2 * cpair + 1][row];
        db[(size_t)(hw_base + row) * (CC / 2) + c2_base + cpair] =
            __floats2half2_rn(lo, hi);
    }
}

// ---------------------------------------------------------------------------
// Kernel 2: FOUR points per warp. 16 unique (point, corner) slots computed in
// one SIMT pass (lanes 16-31 duplicate). 16 independent LDG.64 corner reads
// (MLP=16), HFMA2 accumulation, 2KB contiguous store per warp.
// ---------------------------------------------------------------------------
__global__ __launch_bounds__(256) void gather_kernel(
    const float* __restrict__ tk_codes,   // [B, P, 2]
    float* __restrict__ out)              // [B, P, C]
{
    const unsigned FULL = 0xffffffffu;
    const int quad = (blockIdx.x * blockDim.x + threadIdx.x) >> 5;  // 4-point group
    const int lane = threadIdx.x & 31;

    const int p0 = quad * 4;                 // first point of this warp's quad
    const int j = (lane >> 2) & 3;           // this lane's point within the quad
    const int k = lane & 3;                  // this lane's corner

    // per-lane 8B coord load: 4 distinct addresses -> 1 wavefront
    const float2 pt = __ldg(((const float2*)tk_codes) + p0 + j);
    const float x = pt.x;
    const float y = pt.y;

    const bool inb = (x >= 0.0f) & (y >= 0.0f) &
                     (x <= (float)(WW - 1)) & (y <= (float)(HH - 1));

    // corner order: (fx,fy),(fx,cy),(cx,fy),(cx,cy)
    const float cxk = (k & 2) ? ceilf(x) : floorf(x);
    const float cyk = (k & 1) ? ceilf(y) : floorf(y);

    int gx = ((int)cxk) % WW;   // C-style %: matches jnp.fmod on int32
    int gy = ((int)cyk) % HH;
    gx = max(gx, 0);
    gy = max(gy, 0);

    const float dx = x - (float)gx;
    const float dy = y - (float)gy;
    float w = inb ? __fdividef(1.0f, sqrtf(dx * dx + dy * dy) + 1e-10f) : 0.0f;

    // butterfly within each 4-lane corner group
    float d = w + __shfl_xor_sync(FULL, w, 1);
    d += __shfl_xor_sync(FULL, d, 2);
    if (d == 0.0f) d = 1.0f;
    w *= __fdividef(1.0f, d);               // normalized weight in [0,1]

    const int idx = (gy << 7) + gx;

    // pack (weight-as-half2 duplicated) once per lane
    const unsigned hw2 = h2_to_u32(__float2half2_rn(w));

    const int b = p0 >> 15;                  // P = 32768; quad never spans batches
    // row = 128 ch * 2B = 256B = 32 uint2; lane covers channels [4*lane, 4*lane+4)
    const uint2* __restrict__ baseT =
        (const uint2*)(g_featT + (size_t)b * HW * CC);
    float4* __restrict__ o4 = (float4*)out;

    // process point p: broadcast its 4 corners from lanes p*4+k (width 16)
#pragma unroll
    for (int p = 0; p < 4; p++) {
        const int   s  = p * 4;
        const __half2 w0 = u32_to_h2(__shfl_sync(FULL, hw2, s + 0, 16));
        const __half2 w1 = u32_to_h2(__shfl_sync(FULL, hw2, s + 1, 16));
        const __half2 w2 = u32_to_h2(__shfl_sync(FULL, hw2, s + 2, 16));
        const __half2 w3 = u32_to_h2(__shfl_sync(FULL, hw2, s + 3, 16));
        const int i0 = __shfl_sync(FULL, idx, s + 0, 16);
        const int i1 = __shfl_sync(FULL, idx, s + 1, 16);
        const int i2 = __shfl_sync(FULL, idx, s + 2, 16);
        const int i3 = __shfl_sync(FULL, idx, s + 3, 16);

        const uint2 r0 = baseT[(size_t)i0 * 32 + lane];
        const uint2 r1 = baseT[(size_t)i1 * 32 + lane];
        const uint2 r2 = baseT[(size_t)i2 * 32 + lane];
        const uint2 r3 = baseT[(size_t)i3 * 32 + lane];

        __half2 a0 = __hmul2(w0, u32_to_h2(r0.x));
        __half2 a1 = __hmul2(w0, u32_to_h2(r0.y));
        a0 = __hfma2(w1, u32_to_h2(r1.x), a0);
        a1 = __hfma2(w1, u32_to_h2(r1.y), a1);
        a0 = __hfma2(w2, u32_to_h2(r2.x), a0);
        a1 = __hfma2(w2, u32_to_h2(r2.y), a1);
        a0 = __hfma2(w3, u32_to_h2(r3.x), a0);
        a1 = __hfma2(w3, u32_to_h2(r3.y), a1);

        const float2 f0 = __half22float2(a0);
        const float2 f1 = __half22float2(a1);
        __stcs(o4 + (size_t)(p0 + p) * 32 + lane,
               make_float4(f0.x, f0.y, f1.x, f1.y));
    }
}

// ---------------------------------------------------------------------------
extern "C" void kernel_launch(void* const* d_in, const int* in_sizes, int n_in,
                              void* d_out, int out_size) {
    const float* tk_codes = (const float*)d_in[0];   // [B, P, 2] float32
    const float* feat     = (const float*)d_in[1];   // [B, C, H, W] float32
    float* out            = (float*)d_out;           // [B, P, C] float32

    (void)in_sizes; (void)n_in; (void)out_size;

    dim3 tgrid(HW / 32, CC / 32, BB);
    dim3 tblock(32, 8);
    transpose_kernel<<<tgrid, tblock>>>(feat);

    const int total_quads = BB * PP / 4;         // 65536 quads, 1 warp each
    const int threads = 256;                     // 8 warps/block
    const int blocks = (total_quads * 32) / threads;
    gather_kernel<<<blocks, threads>>>(tk_codes, out);
}

// round 8
// speedup vs baseline: 1.9407x; 1.0406x over previous
#include <cuda_runtime.h>
#include <cuda_fp16.h>
#include <cstdint>

// Problem constants (fixed by the reference)
#define BB 8
#define CC 128
#define HH 128
#define WW 128
#define PP 32768
#define HW (HH * WW)

// Scratch: feat_grid transposed to [B, H*W, C] channels-last, fp16. 33.5 MB.
__device__ __half g_featT[BB * HW * CC];

// bit-cast helpers
static __device__ __forceinline__ unsigned h2_to_u32(__half2 h) {
    return *reinterpret_cast<unsigned*>(&h);
}
static __device__ __forceinline__ __half2 u32_to_h2(unsigned u) {
    return *reinterpret_cast<__half2*>(&u);
}

// ---------------------------------------------------------------------------
// Kernel 1: tiled transpose + f32->fp16:  src[C][HW] -> dstT[HW][C] (half)
// Tile: 32 channels x 128 hw. grid: (HW/128, CC/32, B), block: (32, 8).
// Read phase: float4 loads (512B/warp/instr). 16KB smem tile, pad=1.
// ---------------------------------------------------------------------------
__global__ void transpose_kernel(const float* __restrict__ src) {
    __shared__ float tile[32][129];

    const int b = blockIdx.z;
    const int hw0 = blockIdx.x * 128;
    const int c0 = blockIdx.y * 32;
    const float* sb = src + (size_t)b * CC * HW;
    __half2* db = (__half2*)(g_featT + (size_t)b * HW * CC);

    const int tx = threadIdx.x, ty = threadIdx.y;

    // read: each thread loads 4 float4 (rows c0+ty+8j, cols hw0+4tx..)
#pragma unroll
    for (int jj = 0; jj < 4; jj++) {
        const int c = ty + jj * 8;
        const float4 v = __ldcs((const float4*)&sb[(size_t)(c0 + c) * HW + hw0] + tx);
        tile[c][4 * tx + 0] = v.x;
        tile[c][4 * tx + 1] = v.y;
        tile[c][4 * tx + 2] = v.z;
        tile[c][4 * tx + 3] = v.w;
    }
    __syncthreads();

    // write: thread t -> h2 col (t&15), row group (t>>4); 8 passes of 16 rows
    const int t = ty * 32 + tx;
    const int col = t & 15;          // half2 column within this 32-ch chunk
    const int rowg = t >> 4;         // 0..15
#pragma unroll
    for (int pass = 0; pass < 8; pass++) {
        const int row = rowg + pass * 16;         // local hw row 0..127
        const float lo = tile[2 * col][row];
        const float hi = tile[2 * col + 1][row];
        db[(size_t)(hw0 + row) * (CC / 2) + (c0 >> 1) + col] =
            __floats2half2_rn(lo, hi);
    }
}

// ---------------------------------------------------------------------------
// Kernel 2: EIGHT points per warp. All 32 lanes = unique (point, corner)
// slot -> fully SIMT-efficient corner math. 32 independent LDG.64 corner
// reads (MLP=32), HFMA2 accumulation, 4KB contiguous store per warp.
// ---------------------------------------------------------------------------
__global__ __launch_bounds__(256) void gather_kernel(
    const float* __restrict__ tk_codes,   // [B, P, 2]
    float* __restrict__ out)              // [B, P, C]
{
    const unsigned FULL = 0xffffffffu;
    const int oct = (blockIdx.x * blockDim.x + threadIdx.x) >> 5;  // 8-point group
    const int lane = threadIdx.x & 31;

    const int p0 = oct * 8;                  // first point of this warp's group
    const int j = lane >> 2;                 // this lane's point (0..7)
    const int k = lane & 3;                  // this lane's corner

    // per-lane 8B coord load: 8 distinct addresses -> 64B, 1 wavefront
    const float2 pt = __ldg(((const float2*)tk_codes) + p0 + j);
    const float x = pt.x;
    const float y = pt.y;

    const bool inb = (x >= 0.0f) & (y >= 0.0f) &
                     (x <= (float)(WW - 1)) & (y <= (float)(HH - 1));

    // corner order: (fx,fy),(fx,cy),(cx,fy),(cx,cy)
    const float cxk = (k & 2) ? ceilf(x) : floorf(x);
    const float cyk = (k & 1) ? ceilf(y) : floorf(y);

    int gx = ((int)cxk) % WW;   // C-style %: matches jnp.fmod on int32
    int gy = ((int)cyk) % HH;
    gx = max(gx, 0);
    gy = max(gy, 0);

    const float dx = x - (float)gx;
    const float dy = y - (float)gy;
    float w = inb ? __fdividef(1.0f, sqrtf(dx * dx + dy * dy) + 1e-10f) : 0.0f;

    // butterfly within each 4-lane corner group
    float d = w + __shfl_xor_sync(FULL, w, 1);
    d += __shfl_xor_sync(FULL, d, 2);
    if (d == 0.0f) d = 1.0f;
    w *= __fdividef(1.0f, d);               // normalized weight in [0,1]

    const int idx = (gy << 7) + gx;

    // duplicated-weight half2, packed once per lane
    const unsigned hw2 = h2_to_u32(__float2half2_rn(w));

    const int b = p0 >> 15;                  // P = 32768; group never spans batches
    // row = 128 ch * 2B = 256B = 32 uint2; lane covers channels [4*lane, 4*lane+4)
    const uint2* __restrict__ baseT =
        (const uint2*)(g_featT + (size_t)b * HW * CC);
    float4* __restrict__ o4 = (float4*)out;

#pragma unroll
    for (int p = 0; p < 8; p++) {
        const int s = p * 4;
        const __half2 w0 = u32_to_h2(__shfl_sync(FULL, hw2, s + 0));
        const __half2 w1 = u32_to_h2(__shfl_sync(FULL, hw2, s + 1));
        const __half2 w2 = u32_to_h2(__shfl_sync(FULL, hw2, s + 2));
        const __half2 w3 = u32_to_h2(__shfl_sync(FULL, hw2, s + 3));
        const int i0 = __shfl_sync(FULL, idx, s + 0);
        const int i1 = __shfl_sync(FULL, idx, s + 1);
        const int i2 = __shfl_sync(FULL, idx, s + 2);
        const int i3 = __shfl_sync(FULL, idx, s + 3);

        const uint2 r0 = baseT[(size_t)i0 * 32 + lane];
        const uint2 r1 = baseT[(size_t)i1 * 32 + lane];
        const uint2 r2 = baseT[(size_t)i2 * 32 + lane];
        const uint2 r3 = baseT[(size_t)i3 * 32 + lane];

        __half2 a0 = __hmul2(w0, u32_to_h2(r0.x));
        __half2 a1 = __hmul2(w0, u32_to_h2(r0.y));
        a0 = __hfma2(w1, u32_to_h2(r1.x), a0);
        a1 = __hfma2(w1, u32_to_h2(r1.y), a1);
        a0 = __hfma2(w2, u32_to_h2(r2.x), a0);
        a1 = __hfma2(w2, u32_to_h2(r2.y), a1);
        a0 = __hfma2(w3, u32_to_h2(r3.x), a0);
        a1 = __hfma2(w3, u32_to_h2(r3.y), a1);

        const float2 f0 = __half22float2(a0);
        const float2 f1 = __half22float2(a1);
        __stcs(o4 + (size_t)(p0 + p) * 32 + lane,
               make_float4(f0.x, f0.y, f1.x, f1.y));
    }
}

// ---------------------------------------------------------------------------
extern "C" void kernel_launch(void* const* d_in, const int* in_sizes, int n_in,
                              void* d_out, int out_size) {
    const float* tk_codes = (const float*)d_in[0];   // [B, P, 2] float32
    const float* feat     = (const float*)d_in[1];   // [B, C, H, W] float32
    float* out            = (float*)d_out;           // [B, P, C] float32

    (void)in_sizes; (void)n_in; (void)out_size;

    dim3 tgrid(HW / 128, CC / 32, BB);
    dim3 tblock(32, 8);
    transpose_kernel<<<tgrid, tblock>>>(feat);

    const int total_octs = BB * PP / 8;          // 32768 groups, 1 warp each
    const int threads = 256;                     // 8 warps/block
    const int blocks = (total_octs * 32) / threads;
    gather_kernel<<<blocks, threads>>>(tk_codes, out);
}